// round 1
// baseline (speedup 1.0000x reference)
#include <cuda_runtime.h>

// gltrivmlp: out[b,g,0:16]=con, out[...,16:32]=clip(con*s),
// out[...,32:48]=clip^2, out[...,48:64]=clip^3, s=rowsum(mat[b,g,:])/16.
// The 10-iteration reference loop is a 16-lane shift register that reaches
// this fixed point after 3 iterations; initial val[16:64] is dead.

#define GS    1024
#define PARAM 64

__global__ __launch_bounds__(256, 8)
void gltrivmlp_kernel(const float* __restrict__ mat,
                      const float* __restrict__ val,
                      float* __restrict__ out,
                      int rows)
{
    int warp = (int)((blockIdx.x * (unsigned)blockDim.x + threadIdx.x) >> 5);
    int lane = threadIdx.x & 31;
    if (warp >= rows) return;

    // ---- row sum of mat[row, 0:1024] : 8 independent float4 loads per lane
    const float4* m = reinterpret_cast<const float4*>(mat + (size_t)warp * GS);
    float a0 = 0.f, a1 = 0.f, a2 = 0.f, a3 = 0.f;
    #pragma unroll
    for (int i = 0; i < 8; i += 4) {
        float4 v0 = m[lane + (i + 0) * 32];
        float4 v1 = m[lane + (i + 1) * 32];
        float4 v2 = m[lane + (i + 2) * 32];
        float4 v3 = m[lane + (i + 3) * 32];
        a0 += (v0.x + v0.y) + (v0.z + v0.w);
        a1 += (v1.x + v1.y) + (v1.z + v1.w);
        a2 += (v2.x + v2.y) + (v2.z + v2.w);
        a3 += (v3.x + v3.y) + (v3.z + v3.w);
    }
    float s = (a0 + a1) + (a2 + a3);
    #pragma unroll
    for (int o = 16; o > 0; o >>= 1)
        s += __shfl_xor_sync(0xFFFFFFFFu, s, o);
    float scale = s * (1.0f / 16.0f);

    // ---- each lane produces output elements 2*lane, 2*lane+1 (coalesced float2)
    int e0 = lane << 1;              // even; e0 and e0+1 share the same group
    int g  = e0 >> 4;                // 0..3 clip applications
    const float* con = val + (size_t)warp * PARAM;
    float x0 = con[e0 & 15];
    float x1 = con[(e0 + 1) & 15];
    #pragma unroll
    for (int i = 0; i < 3; i++) {
        if (i < g) {
            x0 = fminf(fmaxf(x0 * scale, -1.0f), 1.0f);
            x1 = fminf(fmaxf(x1 * scale, -1.0f), 1.0f);
        }
    }
    float2* op = reinterpret_cast<float2*>(out + (size_t)warp * PARAM);
    op[lane] = make_float2(x0, x1);
}

extern "C" void kernel_launch(void* const* d_in, const int* in_sizes, int n_in,
                              void* d_out, int out_size)
{
    const float* mat = (const float*)d_in[0];   // (32,1024,1024) f32
    const float* val = (const float*)d_in[1];   // (32,1024,64)  f32
    float* out = (float*)d_out;                 // (32,1024,64)  f32

    int rows = in_sizes[0] / GS;                // 32*1024 = 32768
    int warps_per_block = 256 / 32;             // 8
    int blocks = (rows + warps_per_block - 1) / warps_per_block;
    gltrivmlp_kernel<<<blocks, 256>>>(mat, val, out, rows);
}